// round 2
// baseline (speedup 1.0000x reference)
#include <cuda_runtime.h>
#include <cuda_bf16.h>

// Problem constants
#define B_   16
#define N_   400
#define P_   200
#define EDIM 200
#define ADIM 128
#define H_   8

// Scratch (device globals: no allocation allowed)
__device__ float g_proj[B_ * N_ * ADIM];   // (b,n,a)  3.28 MB
__device__ float g_E[B_ * N_ * EDIM];      // (b,n,e)  5.12 MB

__device__ __forceinline__ float tanh_fast(float x) {
    float y;
    asm("tanh.approx.f32 %0, %1;" : "=f"(y) : "f"(x));
    return y;
}

// ---------------------------------------------------------------------------
// Kernel 1: gather gene embeddings + project E @ W0 + b0
// block = 128 threads (one per output a), 4 rows per block, grid = 1600
// ---------------------------------------------------------------------------
__global__ void k_project(const int* __restrict__ omc,
                          const float* __restrict__ emb_gene,
                          const float* __restrict__ W0,
                          const float* __restrict__ b0) {
    __shared__ float xs[4 * EDIM];
    __shared__ int idxs[4];
    const int t = threadIdx.x;          // 0..127 -> a
    const int row0 = blockIdx.x * 4;    // flat row = b*400 + n

    if (t < 4) idxs[t] = omc[row0 + t];
    __syncthreads();

    // gather 4 rows of 200 floats = 50 float4 each, 200 float4 total
    for (int i = t; i < 4 * (EDIM / 4); i += 128) {
        int r = i / (EDIM / 4), q = i - r * (EDIM / 4);
        float4 v = *(const float4*)(emb_gene + idxs[r] * EDIM + q * 4);
        *(float4*)(xs + r * EDIM + q * 4) = v;
        *(float4*)(g_E + (row0 + r) * EDIM + q * 4) = v;
    }
    __syncthreads();

    float bb0 = b0[t];
    float a0 = bb0, a1 = bb0, a2 = bb0, a3 = bb0;
#pragma unroll 4
    for (int e = 0; e < EDIM; e++) {
        float w = W0[e * ADIM + t];
        a0 += xs[e] * w;
        a1 += xs[EDIM + e] * w;
        a2 += xs[2 * EDIM + e] * w;
        a3 += xs[3 * EDIM + e] * w;
    }
    g_proj[(row0 + 0) * ADIM + t] = a0;
    g_proj[(row0 + 1) * ADIM + t] = a1;
    g_proj[(row0 + 2) * ADIM + t] = a2;
    g_proj[(row0 + 3) * ADIM + t] = a3;
}

// ---------------------------------------------------------------------------
// Kernel 2: fused tanh-attention + softmax + pooling
// grid (50, 16): blockIdx.x = pathway tile (4 pathways), blockIdx.y = b
// block = 256 threads
//
// Smem layout (floats):
//   proj_s [64][132]        8448
//   sc     [4][8][401]     12832   (scores)
//   attn_s [4][400]         1600
//   ep_s   [4][132]          528
//   wb_s   [128*8]          1024
//   red    m[32],rz[32],bb[8] 72
// total 24504 floats = 98016 B  -> 2 blocks/SM
// ---------------------------------------------------------------------------
#define SM_PROJ   0
#define SM_SC     8448
#define SM_ATTN   (8448 + 12832)
#define SM_EP     (SM_ATTN + 1600)
#define SM_WB     (SM_EP + 528)
#define SM_RED    (SM_WB + 1024)
#define SM_TOTALF (SM_RED + 72)

__global__ void __launch_bounds__(256, 2)
k_main(const int* __restrict__ ptw,
       const float* __restrict__ emb_ptw,
       const float* __restrict__ Wb,
       const float* __restrict__ bb,
       float* __restrict__ out) {
    extern __shared__ float sm[];
    float* proj_s = sm + SM_PROJ;
    float* sc     = sm + SM_SC;     // [tp][h][401]
    float* attn_s = sm + SM_ATTN;   // [tp][400]
    float* ep_s   = sm + SM_EP;     // [tp][132]
    float* wb_s   = sm + SM_WB;     // [a*8+h]
    float* red    = sm + SM_RED;    // m[32], rz[32], bb[8]

    const int t  = threadIdx.x;
    const int b  = blockIdx.y;
    const int pt = blockIdx.x;      // pathway tile, 4 pathways

    // init: bb, Wb, Ep
    if (t < H_) red[64 + t] = bb[t];
    for (int i = t; i < ADIM * H_; i += 256) wb_s[i] = Wb[i];
    for (int i = t; i < 4 * ADIM; i += 256) {
        int tp = i >> 7, a = i & 127;
        int pid = ptw[pt * 4 + tp];
        ep_s[tp * 132 + a] = emb_ptw[pid * ADIM + a];
    }

    const int w  = t >> 5;
    const int l  = t & 31;
    const int tp = l >> 3;    // lane's pathway 0..3
    const int l8 = l & 7;     // lane's n within octet

    // -------- score phase: chunks of 64 n --------
    for (int nb = 0; nb < N_; nb += 64) {
        __syncthreads();   // proj_s WAR + (first iter) init visibility
        int nc = N_ - nb; if (nc > 64) nc = 64;
        // stage proj chunk: nc*128 floats = nc*32 float4
        for (int i = t; i < nc * (ADIM / 4); i += 256) {
            int n = i >> 5, q = i & 31;          // q: float4 index within row
            float4 v = *(const float4*)(g_proj + (((b * N_) + nb + n) * ADIM) + q * 4);
            *(float4*)(proj_s + n * 132 + q * 4) = v;
        }
        __syncthreads();

        const int nl = w * 8 + l8;           // n within chunk
        if (nl < nc) {
            float acc0 = red[64 + 0], acc1 = red[64 + 1], acc2 = red[64 + 2], acc3 = red[64 + 3];
            float acc4 = red[64 + 4], acc5 = red[64 + 5], acc6 = red[64 + 6], acc7 = red[64 + 7];
            const float* pr = proj_s + nl * 132;
            const float* ep = ep_s + tp * 132;
#pragma unroll 4
            for (int a = 0; a < ADIM; a++) {
                float x  = pr[a] + ep[a];
                float th = tanh_fast(x);
                float4 wA = *(const float4*)(wb_s + a * 8);
                float4 wB = *(const float4*)(wb_s + a * 8 + 4);
                acc0 += th * wA.x; acc1 += th * wA.y;
                acc2 += th * wA.z; acc3 += th * wA.w;
                acc4 += th * wB.x; acc5 += th * wB.y;
                acc6 += th * wB.z; acc7 += th * wB.w;
            }
            float* sp = sc + tp * (H_ * 401) + (nb + nl);
            sp[0 * 401] = acc0; sp[1 * 401] = acc1; sp[2 * 401] = acc2; sp[3 * 401] = acc3;
            sp[4 * 401] = acc4; sp[5 * 401] = acc5; sp[6 * 401] = acc6; sp[7 * 401] = acc7;
        }
    }
    __syncthreads();

    // -------- softmax reductions: 32 (tp,h) pairs, 8 threads each --------
    {
        const int pair = t >> 3, s8 = t & 7;
        const int ptp = pair >> 3, ph = pair & 7;
        const float* row = sc + ptp * (H_ * 401) + ph * 401;
        float m = -1e30f;
        for (int n = s8; n < N_; n += 8) m = fmaxf(m, row[n]);
#pragma unroll
        for (int d = 4; d; d >>= 1) m = fmaxf(m, __shfl_down_sync(0xffffffffu, m, d, 8));
        m = __shfl_sync(0xffffffffu, m, 0, 8);
        float z = 0.f;
        for (int n = s8; n < N_; n += 8) z += __expf(row[n] - m);
#pragma unroll
        for (int d = 4; d; d >>= 1) z += __shfl_down_sync(0xffffffffu, z, d, 8);
        if (s8 == 0) { red[pair] = m; red[32 + pair] = 1.f / z; }
    }
    __syncthreads();

    // -------- attention weights: attn[tp][n] = sum_h softmax --------
    for (int n = t; n < N_; n += 256) {
#pragma unroll
        for (int tpp = 0; tpp < 4; tpp++) {
            float s = 0.f;
#pragma unroll
            for (int h = 0; h < H_; h++) {
                int pr = tpp * 8 + h;
                s += __expf(sc[tpp * (H_ * 401) + h * 401 + n] - red[pr]) * red[32 + pr];
            }
            attn_s[tpp * N_ + n] = s;
        }
    }
    __syncthreads();

    // -------- pooling: out[b, pt*4+tp, e] = sum_n attn[tp][n] * E[b,n,e] --------
    if (t < EDIM) {
        float o0 = 0.f, o1 = 0.f, o2 = 0.f, o3 = 0.f;
        const float* Eb = g_E + (b * N_) * EDIM + t;
#pragma unroll 4
        for (int n = 0; n < N_; n++) {
            float ev = Eb[n * EDIM];
            o0 += attn_s[n] * ev;
            o1 += attn_s[N_ + n] * ev;
            o2 += attn_s[2 * N_ + n] * ev;
            o3 += attn_s[3 * N_ + n] * ev;
        }
        float* op = out + ((b * P_) + pt * 4) * EDIM + t;
        op[0]        = o0;
        op[EDIM]     = o1;
        op[2 * EDIM] = o2;
        op[3 * EDIM] = o3;
    }
}

// ---------------------------------------------------------------------------
// Launch
// ---------------------------------------------------------------------------
extern "C" void kernel_launch(void* const* d_in, const int* in_sizes, int n_in,
                              void* d_out, int out_size) {
    const int*   omc      = (const int*)d_in[0];   // (B,N)
    const int*   ptw      = (const int*)d_in[1];   // (1,P)
    const float* emb_gene = (const float*)d_in[2]; // (20000,200)
    const float* emb_ptw  = (const float*)d_in[3]; // (1000,128)
    const float* W0       = (const float*)d_in[4]; // (200,128)
    const float* b0       = (const float*)d_in[5]; // (128,)
    const float* Wb       = (const float*)d_in[6]; // (128,8)
    const float* bb       = (const float*)d_in[7]; // (8,)
    float* out = (float*)d_out;                    // (B,P,E)

    const size_t smem_bytes = SM_TOTALF * sizeof(float);
    cudaFuncSetAttribute(k_main, cudaFuncAttributeMaxDynamicSharedMemorySize,
                         (int)smem_bytes);

    k_project<<<(B_ * N_) / 4, 128>>>(omc, emb_gene, W0, b0);
    k_main<<<dim3(P_ / 4, B_), 256, smem_bytes>>>(ptw, emb_ptw, Wb, bb, out);
}

// round 3
// speedup vs baseline: 1.0588x; 1.0588x over previous
#include <cuda_runtime.h>
#include <cuda_fp16.h>
#include <cuda_bf16.h>

// Problem constants
#define B_   16
#define N_   400
#define P_   200
#define EDIM 200
#define ADIM 128
#define H_   8

// Scratch (device globals: no allocation allowed)
__device__ float g_proj[B_ * N_ * ADIM];   // (b,n,a)  3.28 MB
__device__ float g_E[B_ * N_ * EDIM];      // (b,n,e)  5.12 MB

__device__ __forceinline__ float tanh_fast(float x) {
    float y;
    asm("tanh.approx.f32 %0, %1;" : "=f"(y) : "f"(x));
    return y;
}

// ---------------------------------------------------------------------------
// Kernel 1: gather gene embeddings + project E @ W0 + b0
// block = 128 threads (one per output a), 8 rows per block, grid = 800
// ---------------------------------------------------------------------------
__global__ void k_project(const int* __restrict__ omc,
                          const float* __restrict__ emb_gene,
                          const float* __restrict__ W0,
                          const float* __restrict__ b0) {
    __shared__ float xs[8 * EDIM];
    __shared__ int idxs[8];
    const int t = threadIdx.x;          // 0..127 -> a
    const int row0 = blockIdx.x * 8;    // flat row = b*400 + n

    if (t < 8) idxs[t] = omc[row0 + t];
    __syncthreads();

    // gather 8 rows of 200 floats = 50 float4 each, 400 float4 total
    for (int i = t; i < 8 * (EDIM / 4); i += 128) {
        int r = i / (EDIM / 4), q = i - r * (EDIM / 4);
        float4 v = *(const float4*)(emb_gene + idxs[r] * EDIM + q * 4);
        *(float4*)(xs + r * EDIM + q * 4) = v;
        *(float4*)(g_E + (row0 + r) * EDIM + q * 4) = v;
    }
    __syncthreads();

    float bb0 = b0[t];
    float acc[8];
#pragma unroll
    for (int r = 0; r < 8; r++) acc[r] = bb0;
#pragma unroll 2
    for (int e = 0; e < EDIM; e++) {
        float w = W0[e * ADIM + t];
#pragma unroll
        for (int r = 0; r < 8; r++) acc[r] += xs[r * EDIM + e] * w;
    }
#pragma unroll
    for (int r = 0; r < 8; r++)
        g_proj[(row0 + r) * ADIM + t] = acc[r];
}

// ---------------------------------------------------------------------------
// Kernel 2: fused tanh-attention + softmax + pooling
// grid (50, 16): blockIdx.x = pathway tile (4 pathways), blockIdx.y = b
// block = 256 threads
//
// Smem layout (float units):
//   proj_s [64][132]                 8448
//   sc     fp16 [4][8][402]          6432  (12864 halfs)
//   attn_s [4][400]                  1600
//   ep_s   [4][132]                   528
//   wb_s   [128*8]                   1024
//   red    m[32], rz[32], bb[8]        72
// total 18104 floats = 72416 B  -> 3 blocks/SM
// ---------------------------------------------------------------------------
#define SC_STRIDE 402                   /* halfs per (tp,h) row */
#define SM_PROJ   0
#define SM_SC     8448                  /* as half*: 12864 halfs */
#define SM_ATTN   (SM_SC + 6432)
#define SM_EP     (SM_ATTN + 1600)
#define SM_WB     (SM_EP + 528)
#define SM_RED    (SM_WB + 1024)
#define SM_TOTALF (SM_RED + 72)

__global__ void __launch_bounds__(256, 3)
k_main(const int* __restrict__ ptw,
       const float* __restrict__ emb_ptw,
       const float* __restrict__ Wb,
       const float* __restrict__ bb,
       float* __restrict__ out) {
    extern __shared__ float sm[];
    float* proj_s = sm + SM_PROJ;
    __half* sc_h  = (__half*)(sm + SM_SC);  // [tp][h][402]
    float* attn_s = sm + SM_ATTN;           // [tp][400]
    float* ep_s   = sm + SM_EP;             // [tp][132]
    float* wb_s   = sm + SM_WB;             // [a*8+h]
    float* red    = sm + SM_RED;            // m[32], rz[32], bb[8]

    const int t  = threadIdx.x;
    const int b  = blockIdx.y;
    const int pt = blockIdx.x;      // pathway tile, 4 pathways

    // init: bb, Wb, Ep
    if (t < H_) red[64 + t] = bb[t];
    for (int i = t; i < ADIM * H_; i += 256) wb_s[i] = Wb[i];
    for (int i = t; i < 4 * ADIM; i += 256) {
        int tp = i >> 7, a = i & 127;
        int pid = ptw[pt * 4 + tp];
        ep_s[tp * 132 + a] = emb_ptw[pid * ADIM + a];
    }

    const int w  = t >> 5;
    const int l  = t & 31;
    const int tp = l >> 3;    // lane's pathway 0..3
    const int l8 = l & 7;     // lane's n within octet

    // -------- score phase: chunks of 64 n --------
    for (int nb = 0; nb < N_; nb += 64) {
        __syncthreads();   // proj_s WAR + (first iter) init visibility
        int nc = N_ - nb; if (nc > 64) nc = 64;
        // stage proj chunk: nc*128 floats = nc*32 float4
        for (int i = t; i < nc * (ADIM / 4); i += 256) {
            int n = i >> 5, q = i & 31;          // q: float4 index within row
            float4 v = *(const float4*)(g_proj + (((b * N_) + nb + n) * ADIM) + q * 4);
            *(float4*)(proj_s + n * 132 + q * 4) = v;
        }
        __syncthreads();

        const int nl = w * 8 + l8;           // n within chunk
        if (nl < nc) {
            float acc0 = red[64 + 0], acc1 = red[64 + 1], acc2 = red[64 + 2], acc3 = red[64 + 3];
            float acc4 = red[64 + 4], acc5 = red[64 + 5], acc6 = red[64 + 6], acc7 = red[64 + 7];
            const float* pr = proj_s + nl * 132;
            const float* ep = ep_s + tp * 132;
#pragma unroll 4
            for (int a = 0; a < ADIM; a++) {
                float x  = pr[a] + ep[a];
                float th = tanh_fast(x);
                float4 wA = *(const float4*)(wb_s + a * 8);
                float4 wB = *(const float4*)(wb_s + a * 8 + 4);
                acc0 += th * wA.x; acc1 += th * wA.y;
                acc2 += th * wA.z; acc3 += th * wA.w;
                acc4 += th * wB.x; acc5 += th * wB.y;
                acc6 += th * wB.z; acc7 += th * wB.w;
            }
            __half* sp = sc_h + tp * (H_ * SC_STRIDE) + (nb + nl);
            sp[0 * SC_STRIDE] = __float2half(acc0);
            sp[1 * SC_STRIDE] = __float2half(acc1);
            sp[2 * SC_STRIDE] = __float2half(acc2);
            sp[3 * SC_STRIDE] = __float2half(acc3);
            sp[4 * SC_STRIDE] = __float2half(acc4);
            sp[5 * SC_STRIDE] = __float2half(acc5);
            sp[6 * SC_STRIDE] = __float2half(acc6);
            sp[7 * SC_STRIDE] = __float2half(acc7);
        }
    }
    __syncthreads();

    // -------- softmax reductions: 32 (tp,h) pairs, 8 threads each --------
    {
        const int pair = t >> 3, s8 = t & 7;
        const int ptp = pair >> 3, ph = pair & 7;
        const __half* row = sc_h + ptp * (H_ * SC_STRIDE) + ph * SC_STRIDE;
        float m = -1e30f;
        for (int n = s8; n < N_; n += 8) m = fmaxf(m, __half2float(row[n]));
#pragma unroll
        for (int d = 4; d; d >>= 1) m = fmaxf(m, __shfl_down_sync(0xffffffffu, m, d, 8));
        m = __shfl_sync(0xffffffffu, m, 0, 8);
        float z = 0.f;
        for (int n = s8; n < N_; n += 8) z += __expf(__half2float(row[n]) - m);
#pragma unroll
        for (int d = 4; d; d >>= 1) z += __shfl_down_sync(0xffffffffu, z, d, 8);
        if (s8 == 0) { red[pair] = m; red[32 + pair] = 1.f / z; }
    }
    __syncthreads();

    // -------- attention weights: attn[tp][n] = sum_h softmax --------
    for (int n = t; n < N_; n += 256) {
#pragma unroll
        for (int tpp = 0; tpp < 4; tpp++) {
            float s = 0.f;
#pragma unroll
            for (int h = 0; h < H_; h++) {
                int pr = tpp * 8 + h;
                float sv = __half2float(sc_h[tpp * (H_ * SC_STRIDE) + h * SC_STRIDE + n]);
                s += __expf(sv - red[pr]) * red[32 + pr];
            }
            attn_s[tpp * N_ + n] = s;
        }
    }
    __syncthreads();

    // -------- pooling: out[b, pt*4+tp, e] = sum_n attn[tp][n] * E[b,n,e] --------
    if (t < EDIM) {
        float o0 = 0.f, o1 = 0.f, o2 = 0.f, o3 = 0.f;
        const float* Eb = g_E + (b * N_) * EDIM + t;
#pragma unroll 4
        for (int n = 0; n < N_; n++) {
            float ev = Eb[n * EDIM];
            o0 += attn_s[n] * ev;
            o1 += attn_s[N_ + n] * ev;
            o2 += attn_s[2 * N_ + n] * ev;
            o3 += attn_s[3 * N_ + n] * ev;
        }
        float* op = out + ((b * P_) + pt * 4) * EDIM + t;
        op[0]        = o0;
        op[EDIM]     = o1;
        op[2 * EDIM] = o2;
        op[3 * EDIM] = o3;
    }
}

// ---------------------------------------------------------------------------
// Launch
// ---------------------------------------------------------------------------
extern "C" void kernel_launch(void* const* d_in, const int* in_sizes, int n_in,
                              void* d_out, int out_size) {
    const int*   omc      = (const int*)d_in[0];   // (B,N)
    const int*   ptw      = (const int*)d_in[1];   // (1,P)
    const float* emb_gene = (const float*)d_in[2]; // (20000,200)
    const float* emb_ptw  = (const float*)d_in[3]; // (1000,128)
    const float* W0       = (const float*)d_in[4]; // (200,128)
    const float* b0       = (const float*)d_in[5]; // (128,)
    const float* Wb       = (const float*)d_in[6]; // (128,8)
    const float* bb       = (const float*)d_in[7]; // (8,)
    float* out = (float*)d_out;                    // (B,P,E)

    const size_t smem_bytes = SM_TOTALF * sizeof(float);
    cudaFuncSetAttribute(k_main, cudaFuncAttributeMaxDynamicSharedMemorySize,
                         (int)smem_bytes);

    k_project<<<(B_ * N_) / 8, 128>>>(omc, emb_gene, W0, b0);
    k_main<<<dim3(P_ / 4, B_), 256, smem_bytes>>>(ptw, emb_ptw, Wb, bb, out);
}